// round 1
// baseline (speedup 1.0000x reference)
#include <cuda_runtime.h>
#include <stdint.h>

// DayAdapter: y = softsign(x[b] @ W[day_ids[b]] + b[day_ids[b]])
// x: [64, 1024, 512] f32, day_ids: [64] (int32 or int64 — auto-detected),
// W: [24, 512, 512] f32, b: [24, 512] f32, out: [64, 1024, 512] f32.

#define DIMK 512
#define TOK  1024
#define NB   64

#define BM 128
#define BN 128
#define BK 16
#define TM 8
#define TN 8
#define NTHREADS 256

__global__ __launch_bounds__(NTHREADS, 2)
void day_adapter_kernel(const float* __restrict__ x,
                        const int*   __restrict__ day_w,   // raw 32-bit words
                        const float* __restrict__ W,
                        const float* __restrict__ bias,
                        float*       __restrict__ out)
{
    __shared__ float As[BK][BM];   // transposed x tile: As[k][m]
    __shared__ float Bs[BK][BN];   // W tile: Bs[k][n]

    const int bidx = blockIdx.z;

    // --- robust day_ids decode (int32 vs int64 buffer) -------------------
    // If the buffer is little-endian int64, words[1,3,5,...,63] are the high
    // halves of elements 0..31 and are all zero (values < 24). If it is
    // int32, those odd words are the day ids of odd samples — with random
    // ids in [0,24) the probability they are ALL zero is negligible.
    int is64 = 1;
    #pragma unroll 8
    for (int i = 1; i < 64; i += 2) {
        if (__ldg(day_w + i) != 0) is64 = 0;
    }
    const int day = is64 ? __ldg(day_w + 2 * bidx) : __ldg(day_w + bidx);

    const float* A  = x    + (size_t)bidx * TOK * DIMK;   // [1024, 512]
    const float* Bw = W    + (size_t)day  * DIMK * DIMK;  // [512, 512]
    const float* bv = bias + (size_t)day  * DIMK;         // [512]
    float*       C  = out  + (size_t)bidx * TOK * DIMK;

    const int tid  = threadIdx.x;
    const int row0 = blockIdx.y * BM;
    const int col0 = blockIdx.x * BN;

    // A-tile loader mapping: 128 rows x 16 k, float4 along k, 2 rows/thread
    const int aRow = tid >> 2;            // 0..63
    const int aK   = (tid & 3) << 2;      // 0,4,8,12
    // B-tile loader mapping: 16 k x 128 n, float4 along n, 2 k-rows/thread
    const int bRow = tid >> 5;            // 0..7
    const int bCol = (tid & 31) << 2;     // 0..124

    // compute-thread mapping: 16x16 thread grid of 8x8 micro-tiles
    const int ty = tid >> 4;              // 0..15
    const int tx = tid & 15;              // 0..15

    float acc[TM][TN];
    #pragma unroll
    for (int i = 0; i < TM; i++)
        #pragma unroll
        for (int j = 0; j < TN; j++) acc[i][j] = 0.0f;

    for (int k0 = 0; k0 < DIMK; k0 += BK) {
        // ---- load A tile (transpose into As[k][m]) ----
        #pragma unroll
        for (int r = 0; r < 2; r++) {
            const int m = aRow + r * 64;
            float4 v = *reinterpret_cast<const float4*>(
                A + (size_t)(row0 + m) * DIMK + k0 + aK);
            As[aK + 0][m] = v.x;
            As[aK + 1][m] = v.y;
            As[aK + 2][m] = v.z;
            As[aK + 3][m] = v.w;
        }
        // ---- load B tile (direct) ----
        #pragma unroll
        for (int r = 0; r < 2; r++) {
            const int k = bRow + r * 8;
            float4 v = *reinterpret_cast<const float4*>(
                Bw + (size_t)(k0 + k) * DIMK + col0 + bCol);
            *reinterpret_cast<float4*>(&Bs[k][bCol]) = v;
        }
        __syncthreads();

        // ---- FFMA inner loop ----
        #pragma unroll
        for (int k = 0; k < BK; k++) {
            float4 a0 = *reinterpret_cast<const float4*>(&As[k][ty * TM]);
            float4 a1 = *reinterpret_cast<const float4*>(&As[k][ty * TM + 4]);
            float4 b0 = *reinterpret_cast<const float4*>(&Bs[k][tx * TN]);
            float4 b1 = *reinterpret_cast<const float4*>(&Bs[k][tx * TN + 4]);
            float ar[8] = {a0.x, a0.y, a0.z, a0.w, a1.x, a1.y, a1.z, a1.w};
            float br[8] = {b0.x, b0.y, b0.z, b0.w, b1.x, b1.y, b1.z, b1.w};
            #pragma unroll
            for (int i = 0; i < TM; i++)
                #pragma unroll
                for (int j = 0; j < TN; j++)
                    acc[i][j] = fmaf(ar[i], br[j], acc[i][j]);
        }
        __syncthreads();
    }

    // ---- epilogue: bias + softsign, vectorized store ----
    float bb[TN];
    #pragma unroll
    for (int j = 0; j < TN; j++)
        bb[j] = __ldg(bv + col0 + tx * TN + j);

    #pragma unroll
    for (int i = 0; i < TM; i++) {
        float v[8];
        #pragma unroll
        for (int j = 0; j < TN; j++) {
            float y = acc[i][j] + bb[j];
            v[j] = __fdividef(y, 1.0f + fabsf(y));
        }
        const size_t base = (size_t)(row0 + ty * TM + i) * DIMK + col0 + tx * TN;
        *reinterpret_cast<float4*>(C + base)     = make_float4(v[0], v[1], v[2], v[3]);
        *reinterpret_cast<float4*>(C + base + 4) = make_float4(v[4], v[5], v[6], v[7]);
    }
}

extern "C" void kernel_launch(void* const* d_in, const int* in_sizes, int n_in,
                              void* d_out, int out_size)
{
    const float* x   = (const float*)d_in[0];
    const int*   day = (const int*)  d_in[1];
    const float* W   = (const float*)d_in[2];
    const float* b   = (const float*)d_in[3];
    float*       out = (float*)d_out;

    dim3 grid(DIMK / BN, TOK / BM, NB);   // (4, 8, 64) = 2048 blocks
    day_adapter_kernel<<<grid, NTHREADS>>>(x, day, W, b, out);
}

// round 3
// speedup vs baseline: 1.6063x; 1.6063x over previous
#include <cuda_runtime.h>
#include <cuda_bf16.h>
#include <stdint.h>

// DayAdapter via mma.sync (sm_103 base ISA — tcgen05 unavailable in this toolchain).
// y = softsign(x@W[day] + b[day]) = softsign(x + x@E + b),  E = W - I  (|E|~0.02)
// x split hi/lo bf16: y = x + xh@E + xl@E  (2 bf16 GEMMs, fp32 accumulate)

#define DIMK 512
#define TOK  1024
#define NB   64
#define NDAYS 24

#define CTA_M 128
#define CTA_N 128
#define BK    32
#define KSTEPS (DIMK / BK)       // 16
#define NTHREADS 256             // 8 warps: 2(m) x 4(n), warp tile 64x32

// SMEM stage: Ah 8KB | Al 8KB | B 8KB  (rows of 32 bf16 = 64B, 4x16B chunks)
#define STG_BYTES 24576
#define OFF_AH 0
#define OFF_AL 8192
#define OFF_B  16384
#define SMEM_TOTAL (2 * STG_BYTES)   // 49152

// E = W - I, transposed: [day][n][k] bf16
__device__ __nv_bfloat16 g_Et[(size_t)NDAYS * DIMK * DIMK];

// ---------------- helpers ----------------
__device__ __forceinline__ uint32_t smem_u32(const void* p) {
    return (uint32_t)__cvta_generic_to_shared(p);
}
// swizzled byte offset of (row, 16B-chunk) in a 64B-row tile
__device__ __forceinline__ uint32_t swz(uint32_t row, uint32_t ch) {
    return row * 64u + ((ch ^ ((row >> 1) & 3u)) << 4);
}
__device__ __forceinline__ void ldsm_x4(uint32_t* r, uint32_t addr) {
    asm volatile("ldmatrix.sync.aligned.m8n8.x4.shared.b16 {%0,%1,%2,%3}, [%4];"
                 : "=r"(r[0]), "=r"(r[1]), "=r"(r[2]), "=r"(r[3]) : "r"(addr));
}
__device__ __forceinline__ void mma_bf16(float* c, const uint32_t* a, uint32_t b0, uint32_t b1) {
    asm volatile(
        "mma.sync.aligned.m16n8k16.row.col.f32.bf16.bf16.f32 "
        "{%0,%1,%2,%3}, {%4,%5,%6,%7}, {%8,%9}, {%0,%1,%2,%3};"
        : "+f"(c[0]), "+f"(c[1]), "+f"(c[2]), "+f"(c[3])
        : "r"(a[0]), "r"(a[1]), "r"(a[2]), "r"(a[3]), "r"(b0), "r"(b1));
}
__device__ __forceinline__ void cp_async16(uint32_t dst, const void* src) {
    asm volatile("cp.async.cg.shared.global [%0], [%1], 16;" :: "r"(dst), "l"(src));
}
__device__ __forceinline__ void cp_commit() { asm volatile("cp.async.commit_group;"); }
__device__ __forceinline__ void cp_wait1()  { asm volatile("cp.async.wait_group 1;"); }
__device__ __forceinline__ void cp_wait0()  { asm volatile("cp.async.wait_group 0;"); }

// pack two floats' bf16-hi and bf16-lo parts
__device__ __forceinline__ void split2(float a, float b, uint32_t& hi, uint32_t& lo) {
    __nv_bfloat16 ha = __float2bfloat16_rn(a);
    __nv_bfloat16 hb = __float2bfloat16_rn(b);
    __nv_bfloat16 la = __float2bfloat16_rn(a - __bfloat162float(ha));
    __nv_bfloat16 lb = __float2bfloat16_rn(b - __bfloat162float(hb));
    hi = ((uint32_t)__bfloat16_as_ushort(hb) << 16) | (uint32_t)__bfloat16_as_ushort(ha);
    lo = ((uint32_t)__bfloat16_as_ushort(lb) << 16) | (uint32_t)__bfloat16_as_ushort(la);
}

// ---------------- prep: Et[d][n][k] = bf16(W[d][k][n] - (k==n)) ----------------
__global__ void prep_e_kernel(const float* __restrict__ W) {
    __shared__ float t[32][33];
    const int d  = blockIdx.z;
    const int k0 = blockIdx.y * 32;
    const int n0 = blockIdx.x * 32;
    const float* Wd = W + (size_t)d * DIMK * DIMK;
    #pragma unroll
    for (int i = threadIdx.y; i < 32; i += 8)
        t[i][threadIdx.x] = Wd[(size_t)(k0 + i) * DIMK + n0 + threadIdx.x];
    __syncthreads();
    #pragma unroll
    for (int i = threadIdx.y; i < 32; i += 8) {
        const int k = k0 + threadIdx.x;
        const int n = n0 + i;
        float v = t[threadIdx.x][i] - ((k == n) ? 1.0f : 0.0f);
        g_Et[((size_t)d * DIMK + n) * DIMK + k] = __float2bfloat16_rn(v);
    }
}

// ---------------- main ----------------
__global__ void __launch_bounds__(NTHREADS, 1)
day_adapter_hmma(const float* __restrict__ x,
                 const int*   __restrict__ day_w,
                 const float* __restrict__ bias,
                 float*       __restrict__ out)
{
    extern __shared__ char smem[];
    const uint32_t sb = smem_u32(smem);
    const int tid  = threadIdx.x;
    const int wid  = tid >> 5;
    const int lane = tid & 31;

    const int n0   = blockIdx.x * CTA_N;
    const int m0   = blockIdx.y * CTA_M;
    const int bidx = blockIdx.z;

    // robust day_ids decode (int32 vs int64 buffer)
    int is64 = 1;
    #pragma unroll 8
    for (int i = 1; i < 64; i += 2)
        if (__ldg(day_w + i) != 0) is64 = 0;
    const int day = is64 ? __ldg(day_w + 2 * bidx) : __ldg(day_w + bidx);

    // -------- loaders --------
    // A: thread -> (row = tid>>1, half = tid&1): 16 fp32 = 4 float4
    const int arow = tid >> 1;
    const int ahalf = tid & 1;
    const float4* agp = (const float4*)(x + ((size_t)bidx * TOK + m0 + arow) * DIMK) + ahalf * 4;
    // B: thread -> chunks 2t, 2t+1: row = t>>1, chunk = (t&1)*2 + {0,1}
    const int brow = tid >> 1;
    const int bch0 = (tid & 1) * 2;
    const __nv_bfloat16* bgp = g_Et + ((size_t)day * DIMK + n0 + brow) * DIMK;

    float4 ra[2][4];

    auto LDGA = [&](int s, int bank) {
        #pragma unroll
        for (int c = 0; c < 4; c++) ra[bank][c] = __ldg(agp + s * 8 + c);
    };
    auto STSA = [&](int s, int bank) {
        char* stg = smem + (s & 1) * STG_BYTES;
        uint4 hv, lv;
        split2(ra[bank][0].x, ra[bank][0].y, hv.x, lv.x);
        split2(ra[bank][0].z, ra[bank][0].w, hv.y, lv.y);
        split2(ra[bank][1].x, ra[bank][1].y, hv.z, lv.z);
        split2(ra[bank][1].z, ra[bank][1].w, hv.w, lv.w);
        uint32_t o = swz(arow, ahalf * 2);
        *(uint4*)(stg + OFF_AH + o) = hv;
        *(uint4*)(stg + OFF_AL + o) = lv;
        split2(ra[bank][2].x, ra[bank][2].y, hv.x, lv.x);
        split2(ra[bank][2].z, ra[bank][2].w, hv.y, lv.y);
        split2(ra[bank][3].x, ra[bank][3].y, hv.z, lv.z);
        split2(ra[bank][3].z, ra[bank][3].w, hv.w, lv.w);
        o = swz(arow, ahalf * 2 + 1);
        *(uint4*)(stg + OFF_AH + o) = hv;
        *(uint4*)(stg + OFF_AL + o) = lv;
    };
    auto CAB = [&](int s) {
        const uint32_t dst = sb + (s & 1) * STG_BYTES + OFF_B;
        cp_async16(dst + swz(brow, bch0),     bgp + s * BK + bch0 * 8);
        cp_async16(dst + swz(brow, bch0 + 1), bgp + s * BK + bch0 * 8 + 8);
        cp_commit();
    };

    // -------- warp tile coords --------
    const int mw = (wid >> 2) * 64;        // warp m offset in CTA
    const int nw = (wid & 3) * 32;         // warp n offset in CTA

    float acc[4][4][4];
    #pragma unroll
    for (int i = 0; i < 4; i++)
        #pragma unroll
        for (int j = 0; j < 4; j++)
            #pragma unroll
            for (int q = 0; q < 4; q++) acc[i][j][q] = 0.0f;

    // ldmatrix lane addressing (precompute row/chunk pieces)
    const int a_lrow = lane & 15;          // + m tile base
    const int a_lch  = lane >> 4;          // + 2*k2
    const int b_lrow = (lane & 7) + ((lane >> 4) << 3);
    const int b_lch  = (lane >> 3) & 1;    // + 2*k2

    // -------- prolog --------
    LDGA(0, 0); LDGA(1, 1);
    CAB(0); CAB(1);
    STSA(0, 0);
    cp_wait1();
    __syncthreads();

    // -------- main loop --------
    for (int s = 0; s < KSTEPS; s++) {
        const uint32_t stg = sb + (s & 1) * STG_BYTES;

        if (s + 1 < KSTEPS) STSA(s + 1, (s + 1) & 1);
        if (s + 2 < KSTEPS) LDGA(s + 2, s & 1);

        #pragma unroll
        for (int k2 = 0; k2 < 2; k2++) {
            uint32_t bf[2][4];
            #pragma unroll
            for (int pair = 0; pair < 2; pair++)
                ldsm_x4(bf[pair], stg + OFF_B + swz(nw + pair * 16 + b_lrow, 2 * k2 + b_lch));
            uint32_t ah[4][4], al[4][4];
            #pragma unroll
            for (int mt = 0; mt < 4; mt++) {
                const uint32_t o = swz(mw + mt * 16 + a_lrow, 2 * k2 + a_lch);
                ldsm_x4(ah[mt], stg + OFF_AH + o);
                ldsm_x4(al[mt], stg + OFF_AL + o);
            }
            #pragma unroll
            for (int mt = 0; mt < 4; mt++)
                #pragma unroll
                for (int nt = 0; nt < 4; nt++) {
                    const uint32_t b0 = bf[nt >> 1][(nt & 1) * 2];
                    const uint32_t b1 = bf[nt >> 1][(nt & 1) * 2 + 1];
                    mma_bf16(acc[mt][nt], ah[mt], b0, b1);
                    mma_bf16(acc[mt][nt], al[mt], b0, b1);
                }
        }

        __syncthreads();                      // all warps done reading this stage
        if (s + 2 < KSTEPS) CAB(s + 2);       // refill B region of this buffer
        if (s + 1 < KSTEPS) {
            if (s + 2 < KSTEPS) cp_wait1(); else cp_wait0();
            __syncthreads();                  // B(s+1) visible to all
        }
    }

    // -------- epilogue: y = x + acc + bias; softsign; store --------
    const int r  = lane >> 2;
    const int cq = (lane & 3) * 2;
    const float* xep = x + (size_t)bidx * TOK * DIMK;
    const float* bp  = bias + (size_t)day * DIMK;

    #pragma unroll
    for (int nt = 0; nt < 4; nt++) {
        const int n = n0 + nw + nt * 8 + cq;
        const float2 bb = *(const float2*)(bp + n);
        #pragma unroll
        for (int mt = 0; mt < 4; mt++) {
            const int m = m0 + mw + mt * 16 + r;
            const float2 x0 = __ldg((const float2*)(xep + (size_t)m * DIMK + n));
            const float2 x1 = __ldg((const float2*)(xep + (size_t)(m + 8) * DIMK + n));
            float y0 = acc[mt][nt][0] + x0.x + bb.x;
            float y1 = acc[mt][nt][1] + x0.y + bb.y;
            float y2 = acc[mt][nt][2] + x1.x + bb.x;
            float y3 = acc[mt][nt][3] + x1.y + bb.y;
            float2 o0, o1;
            o0.x = __fdividef(y0, 1.0f + fabsf(y0));
            o0.y = __fdividef(y1, 1.0f + fabsf(y1));
            o1.x = __fdividef(y2, 1.0f + fabsf(y2));
            o1.y = __fdividef(y3, 1.0f + fabsf(y3));
            *(float2*)(out + (size_t)bidx * TOK * DIMK + (size_t)m * DIMK + n)       = o0;
            *(float2*)(out + (size_t)bidx * TOK * DIMK + (size_t)(m + 8) * DIMK + n) = o1;
        }
    }
}

// ---------------- launch ----------------
extern "C" void kernel_launch(void* const* d_in, const int* in_sizes, int n_in,
                              void* d_out, int out_size)
{
    const float* x   = (const float*)d_in[0];
    const int*   day = (const int*)  d_in[1];
    const float* W   = (const float*)d_in[2];
    const float* b   = (const float*)d_in[3];
    float*       out = (float*)d_out;

    cudaFuncSetAttribute(day_adapter_hmma,
                         cudaFuncAttributeMaxDynamicSharedMemorySize, SMEM_TOTAL);

    prep_e_kernel<<<dim3(DIMK / 32, DIMK / 32, NDAYS), dim3(32, 8)>>>(W);

    dim3 grid(DIMK / CTA_N, TOK / CTA_M, NB);   // (4, 8, 64) = 2048 CTAs
    day_adapter_hmma<<<grid, NTHREADS, SMEM_TOTAL>>>(x, day, b, out);
}

// round 4
// speedup vs baseline: 2.6538x; 1.6521x over previous
#include <cuda_runtime.h>
#include <cuda_bf16.h>
#include <stdint.h>

// DayAdapter via tf32 mma.sync: y = softsign(x + x@E + b), E = W - I (|E|~0.02).
// Single tf32 GEMM (x rounded RNA to tf32; E pre-rounded in prep kernel).
// 3-stage cp.async pipeline, one __syncthreads/stage, 2 CTAs/SM.

#define DIMK 512
#define TOK  1024
#define NB   64
#define NDAYS 24

#define CTA_M 128
#define CTA_N 128
#define BK    32
#define KSTEPS (DIMK / BK)       // 16
#define NTHREADS 256             // 8 warps: 2(m) x 4(n), warp tile 64x32
#define STAGES 3

// Stage: A 128x32 f32 (16KB) | B 128x32 f32 (16KB); rows 128B = 8 x 16B chunks
#define STG_BYTES 32768
#define OFF_A 0
#define OFF_B 16384
#define SMEM_TOTAL (STAGES * STG_BYTES)   // 98304

// E = W - I, transposed [day][n][k], tf32-rounded f32 bits
__device__ float g_Et[(size_t)NDAYS * DIMK * DIMK];

// ---------------- helpers ----------------
__device__ __forceinline__ uint32_t smem_u32(const void* p) {
    return (uint32_t)__cvta_generic_to_shared(p);
}
// swizzled byte offset: 128B rows, chunk ^= (row & 7)
__device__ __forceinline__ uint32_t swz(uint32_t row, uint32_t ch) {
    return row * 128u + ((ch ^ (row & 7u)) << 4);
}
__device__ __forceinline__ void ldsm_x4(uint32_t* r, uint32_t addr) {
    asm volatile("ldmatrix.sync.aligned.m8n8.x4.shared.b16 {%0,%1,%2,%3}, [%4];"
                 : "=r"(r[0]), "=r"(r[1]), "=r"(r[2]), "=r"(r[3]) : "r"(addr));
}
__device__ __forceinline__ void mma_tf32(float* c, const uint32_t* a, uint32_t b0, uint32_t b1) {
    asm volatile(
        "mma.sync.aligned.m16n8k8.row.col.f32.tf32.tf32.f32 "
        "{%0,%1,%2,%3}, {%4,%5,%6,%7}, {%8,%9}, {%0,%1,%2,%3};"
        : "+f"(c[0]), "+f"(c[1]), "+f"(c[2]), "+f"(c[3])
        : "r"(a[0]), "r"(a[1]), "r"(a[2]), "r"(a[3]), "r"(b0), "r"(b1));
}
__device__ __forceinline__ uint32_t f2tf32(uint32_t v) {
    uint32_t o;
    asm("cvt.rna.tf32.f32 %0, %1;" : "=r"(o) : "r"(v));
    return o;
}
__device__ __forceinline__ void cp_async16(uint32_t dst, const void* src) {
    asm volatile("cp.async.cg.shared.global [%0], [%1], 16;" :: "r"(dst), "l"(src));
}
__device__ __forceinline__ void cp_commit() { asm volatile("cp.async.commit_group;"); }
__device__ __forceinline__ void cp_wait1()  { asm volatile("cp.async.wait_group 1;"); }

// ---------------- prep: Et[d][n][k] = tf32(W[d][k][n] - (k==n)) ----------------
__global__ void prep_e_kernel(const float* __restrict__ W) {
    __shared__ float t[32][33];
    const int d  = blockIdx.z;
    const int k0 = blockIdx.y * 32;
    const int n0 = blockIdx.x * 32;
    const float* Wd = W + (size_t)d * DIMK * DIMK;
    #pragma unroll
    for (int i = threadIdx.y; i < 32; i += 8)
        t[i][threadIdx.x] = Wd[(size_t)(k0 + i) * DIMK + n0 + threadIdx.x];
    __syncthreads();
    #pragma unroll
    for (int i = threadIdx.y; i < 32; i += 8) {
        const int k = k0 + threadIdx.x;
        const int n = n0 + i;
        float v = t[threadIdx.x][i] - ((k == n) ? 1.0f : 0.0f);
        uint32_t r = f2tf32(__float_as_uint(v));
        g_Et[((size_t)d * DIMK + n) * DIMK + k] = __uint_as_float(r);
    }
}

// ---------------- main ----------------
__global__ void __launch_bounds__(NTHREADS, 2)
day_adapter_tf32(const float* __restrict__ x,
                 const int*   __restrict__ day_w,
                 const float* __restrict__ bias,
                 float*       __restrict__ out)
{
    extern __shared__ char smem[];
    const uint32_t sb = smem_u32(smem);
    const int tid  = threadIdx.x;
    const int wid  = tid >> 5;
    const int lane = tid & 31;

    const int n0   = blockIdx.x * CTA_N;
    const int m0   = blockIdx.y * CTA_M;
    const int bidx = blockIdx.z;

    // robust day_ids decode (int32 vs int64 buffer)
    int is64 = 1;
    #pragma unroll 8
    for (int i = 1; i < 64; i += 2)
        if (__ldg(day_w + i) != 0) is64 = 0;
    const int day = is64 ? __ldg(day_w + 2 * bidx) : __ldg(day_w + bidx);

    // -------- stage loaders: thread t -> row=t>>1, chunks (t&1)*4 .. +3 --------
    const int lrow = tid >> 1;
    const int lc0  = (tid & 1) * 4;
    const float* agp = x    + ((size_t)bidx * TOK + m0 + lrow) * DIMK + lc0 * 4;
    const float* bgp = g_Et + ((size_t)day  * DIMK + n0 + lrow) * DIMK + lc0 * 4;

    auto LOAD_STAGE = [&](int s) {
        const uint32_t stg = sb + (s % STAGES) * STG_BYTES;
        const float* asrc = agp + s * BK;
        const float* bsrc = bgp + s * BK;
        #pragma unroll
        for (int c = 0; c < 4; c++) {
            const uint32_t o = swz(lrow, lc0 + c);
            cp_async16(stg + OFF_A + o, asrc + c * 4);
            cp_async16(stg + OFF_B + o, bsrc + c * 4);
        }
    };

    // -------- warp tile --------
    const int mw = (wid >> 2) * 64;
    const int nw = (wid & 3) * 32;

    float acc[4][4][4];
    #pragma unroll
    for (int i = 0; i < 4; i++)
        #pragma unroll
        for (int j = 0; j < 4; j++)
            #pragma unroll
            for (int q = 0; q < 4; q++) acc[i][j][q] = 0.0f;

    // ldmatrix lane addressing
    const int a_row = mw + (lane & 15);          // + mt*16
    const int a_ch  = lane >> 4;                 // + 2*k2
    const int b_row = nw + (lane & 7) + ((lane >> 4) << 3);  // + np*16
    const int b_ch  = (lane >> 3) & 1;           // + 2*k2

    // -------- prolog --------
    LOAD_STAGE(0); cp_commit();
    LOAD_STAGE(1); cp_commit();

    // -------- main loop: one __syncthreads per stage --------
    for (int s = 0; s < KSTEPS; s++) {
        cp_wait1();
        __syncthreads();                 // stage s ready; stage s-1 buffer free

        if (s + 2 < KSTEPS) LOAD_STAGE(s + 2);
        cp_commit();                     // (possibly empty) keep group count aligned

        const uint32_t stg = sb + (s % STAGES) * STG_BYTES;
        #pragma unroll
        for (int k2 = 0; k2 < 4; k2++) {
            uint32_t bf[2][4];
            #pragma unroll
            for (int np = 0; np < 2; np++)
                ldsm_x4(bf[np], stg + OFF_B + swz(b_row + np * 16, 2 * k2 + b_ch));
            uint32_t af[4][4];
            #pragma unroll
            for (int mt = 0; mt < 4; mt++) {
                ldsm_x4(af[mt], stg + OFF_A + swz(a_row + mt * 16, 2 * k2 + a_ch));
                #pragma unroll
                for (int q = 0; q < 4; q++) af[mt][q] = f2tf32(af[mt][q]);
            }
            #pragma unroll
            for (int mt = 0; mt < 4; mt++)
                #pragma unroll
                for (int nt = 0; nt < 4; nt++)
                    mma_tf32(acc[mt][nt], af[mt],
                             bf[nt >> 1][(nt & 1) * 2], bf[nt >> 1][(nt & 1) * 2 + 1]);
        }
    }

    // -------- epilogue: y = x + acc + bias; softsign --------
    const int r  = lane >> 2;
    const int cq = (lane & 3) * 2;
    const float* xep = x + (size_t)bidx * TOK * DIMK;
    const float* bp  = bias + (size_t)day * DIMK;

    #pragma unroll
    for (int nt = 0; nt < 4; nt++) {
        const int n = n0 + nw + nt * 8 + cq;
        const float2 bb = *(const float2*)(bp + n);
        #pragma unroll
        for (int mt = 0; mt < 4; mt++) {
            const int m = m0 + mw + mt * 16 + r;
            const float2 x0 = __ldg((const float2*)(xep + (size_t)m * DIMK + n));
            const float2 x1 = __ldg((const float2*)(xep + (size_t)(m + 8) * DIMK + n));
            float y0 = acc[mt][nt][0] + x0.x + bb.x;
            float y1 = acc[mt][nt][1] + x0.y + bb.y;
            float y2 = acc[mt][nt][2] + x1.x + bb.x;
            float y3 = acc[mt][nt][3] + x1.y + bb.y;
            float2 o0, o1;
            o0.x = __fdividef(y0, 1.0f + fabsf(y0));
            o0.y = __fdividef(y1, 1.0f + fabsf(y1));
            o1.x = __fdividef(y2, 1.0f + fabsf(y2));
            o1.y = __fdividef(y3, 1.0f + fabsf(y3));
            *(float2*)(out + (size_t)bidx * TOK * DIMK + (size_t)m * DIMK + n)       = o0;
            *(float2*)(out + (size_t)bidx * TOK * DIMK + (size_t)(m + 8) * DIMK + n) = o1;
        }
    }
}

// ---------------- launch ----------------
extern "C" void kernel_launch(void* const* d_in, const int* in_sizes, int n_in,
                              void* d_out, int out_size)
{
    const float* x   = (const float*)d_in[0];
    const int*   day = (const int*)  d_in[1];
    const float* W   = (const float*)d_in[2];
    const float* b   = (const float*)d_in[3];
    float*       out = (float*)d_out;

    cudaFuncSetAttribute(day_adapter_tf32,
                         cudaFuncAttributeMaxDynamicSharedMemorySize, SMEM_TOTAL);

    prep_e_kernel<<<dim3(DIMK / 32, DIMK / 32, NDAYS), dim3(32, 8)>>>(W);

    dim3 grid(DIMK / CTA_N, TOK / CTA_M, NB);   // (4, 8, 64) = 2048 CTAs
    day_adapter_tf32<<<grid, NTHREADS, SMEM_TOTAL>>>(x, day, b, out);
}

// round 5
// speedup vs baseline: 2.7555x; 1.0383x over previous
#include <cuda_runtime.h>
#include <cuda_bf16.h>
#include <stdint.h>

// DayAdapter via tf32 mma.sync: y = softsign(x + x@E + b), E = W - I (|E|~0.02).
// Raw fp32 fed to tf32 MMA (HW ignores low 13 mantissa bits => implicit RZ on x);
// E pre-rounded RNA in prep kernel. 3-stage cp.async pipeline, 2 CTAs/SM.

#define DIMK 512
#define TOK  1024
#define NB   64
#define NDAYS 24

#define CTA_M 128
#define CTA_N 128
#define BK    32
#define KSTEPS (DIMK / BK)       // 16
#define NTHREADS 256             // 8 warps: 2(m) x 4(n), warp tile 64x32
#define STAGES 3

// Stage: A 128x32 f32 (16KB) | B 128x32 f32 (16KB); rows 128B = 8 x 16B chunks
#define STG_BYTES 32768
#define OFF_A 0
#define OFF_B 16384
#define SMEM_TOTAL (STAGES * STG_BYTES)   // 98304

// E = W - I, transposed [day][n][k], tf32-rounded f32 bits
__device__ float g_Et[(size_t)NDAYS * DIMK * DIMK];

// ---------------- helpers ----------------
__device__ __forceinline__ uint32_t smem_u32(const void* p) {
    return (uint32_t)__cvta_generic_to_shared(p);
}
// swizzled byte offset: 128B rows, chunk ^= (row & 7)
__device__ __forceinline__ uint32_t swz(uint32_t row, uint32_t ch) {
    return row * 128u + ((ch ^ (row & 7u)) << 4);
}
__device__ __forceinline__ void ldsm_x4(uint32_t* r, uint32_t addr) {
    asm volatile("ldmatrix.sync.aligned.m8n8.x4.shared.b16 {%0,%1,%2,%3}, [%4];"
                 : "=r"(r[0]), "=r"(r[1]), "=r"(r[2]), "=r"(r[3]) : "r"(addr));
}
__device__ __forceinline__ void mma_tf32(float* c, const uint32_t* a, uint32_t b0, uint32_t b1) {
    asm volatile(
        "mma.sync.aligned.m16n8k8.row.col.f32.tf32.tf32.f32 "
        "{%0,%1,%2,%3}, {%4,%5,%6,%7}, {%8,%9}, {%0,%1,%2,%3};"
        : "+f"(c[0]), "+f"(c[1]), "+f"(c[2]), "+f"(c[3])
        : "r"(a[0]), "r"(a[1]), "r"(a[2]), "r"(a[3]), "r"(b0), "r"(b1));
}
__device__ __forceinline__ uint32_t f2tf32(uint32_t v) {
    uint32_t o;
    asm("cvt.rna.tf32.f32 %0, %1;" : "=r"(o) : "r"(v));
    return o;
}
__device__ __forceinline__ void cp_async16(uint32_t dst, const void* src) {
    asm volatile("cp.async.cg.shared.global [%0], [%1], 16;" :: "r"(dst), "l"(src));
}
__device__ __forceinline__ void cp_commit() { asm volatile("cp.async.commit_group;"); }
__device__ __forceinline__ void cp_wait1()  { asm volatile("cp.async.wait_group 1;"); }

// ---------------- prep: Et[d][n][k] = tf32_rna(W[d][k][n] - (k==n)) ----------------
__global__ void prep_e_kernel(const float* __restrict__ W) {
    __shared__ float t[32][33];
    const int d  = blockIdx.z;
    const int k0 = blockIdx.y * 32;
    const int n0 = blockIdx.x * 32;
    const float* Wd = W + (size_t)d * DIMK * DIMK;
    #pragma unroll
    for (int i = threadIdx.y; i < 32; i += 8)
        t[i][threadIdx.x] = Wd[(size_t)(k0 + i) * DIMK + n0 + threadIdx.x];
    __syncthreads();
    #pragma unroll
    for (int i = threadIdx.y; i < 32; i += 8) {
        const int k = k0 + threadIdx.x;
        const int n = n0 + i;
        float v = t[threadIdx.x][i] - ((k == n) ? 1.0f : 0.0f);
        uint32_t r = f2tf32(__float_as_uint(v));
        g_Et[((size_t)d * DIMK + n) * DIMK + k] = __uint_as_float(r);
    }
}

// ---------------- main ----------------
__global__ void __launch_bounds__(NTHREADS, 2)
day_adapter_tf32(const float* __restrict__ x,
                 const int*   __restrict__ day_w,
                 const float* __restrict__ bias,
                 float*       __restrict__ out)
{
    extern __shared__ char smem[];
    const uint32_t sb = smem_u32(smem);
    const int tid  = threadIdx.x;
    const int wid  = tid >> 5;
    const int lane = tid & 31;

    const int n0   = blockIdx.x * CTA_N;
    const int m0   = blockIdx.y * CTA_M;
    const int bidx = blockIdx.z;

    // robust day_ids decode (int32 vs int64 buffer)
    int is64 = 1;
    #pragma unroll 8
    for (int i = 1; i < 64; i += 2)
        if (__ldg(day_w + i) != 0) is64 = 0;
    const int day = is64 ? __ldg(day_w + 2 * bidx) : __ldg(day_w + bidx);

    // -------- stage loaders: thread t -> row=t>>1, chunks (t&1)*4 .. +3 --------
    const int lrow = tid >> 1;
    const int lc0  = (tid & 1) * 4;
    const float* agp = x    + ((size_t)bidx * TOK + m0 + lrow) * DIMK + lc0 * 4;
    const float* bgp = g_Et + ((size_t)day  * DIMK + n0 + lrow) * DIMK + lc0 * 4;

    auto LOAD_STAGE = [&](int s) {
        const uint32_t stg = sb + (s % STAGES) * STG_BYTES;
        const float* asrc = agp + s * BK;
        const float* bsrc = bgp + s * BK;
        #pragma unroll
        for (int c = 0; c < 4; c++) {
            const uint32_t o = swz(lrow, lc0 + c);
            cp_async16(stg + OFF_A + o, asrc + c * 4);
            cp_async16(stg + OFF_B + o, bsrc + c * 4);
        }
    };

    // -------- warp tile --------
    const int mw = (wid >> 2) * 64;
    const int nw = (wid & 3) * 32;

    float acc[4][4][4];
    #pragma unroll
    for (int i = 0; i < 4; i++)
        #pragma unroll
        for (int j = 0; j < 4; j++)
            #pragma unroll
            for (int q = 0; q < 4; q++) acc[i][j][q] = 0.0f;

    // ldmatrix lane addressing
    const int a_row = mw + (lane & 15);          // + mt*16
    const int a_ch  = lane >> 4;                 // + 2*k2
    const int b_row = nw + (lane & 7) + ((lane >> 4) << 3);  // + np*16
    const int b_ch  = (lane >> 3) & 1;           // + 2*k2

    // -------- prolog --------
    LOAD_STAGE(0); cp_commit();
    LOAD_STAGE(1); cp_commit();

    // -------- main loop: one __syncthreads per stage --------
    for (int s = 0; s < KSTEPS; s++) {
        cp_wait1();
        __syncthreads();                 // stage s ready; stage s-1 buffer free

        if (s + 2 < KSTEPS) LOAD_STAGE(s + 2);
        cp_commit();                     // keep group count aligned

        const uint32_t stg = sb + (s % STAGES) * STG_BYTES;
        #pragma unroll
        for (int k2 = 0; k2 < 4; k2++) {
            uint32_t bf[2][4];
            #pragma unroll
            for (int np = 0; np < 2; np++)
                ldsm_x4(bf[np], stg + OFF_B + swz(b_row + np * 16, 2 * k2 + b_ch));
            uint32_t af[4][4];
            #pragma unroll
            for (int mt = 0; mt < 4; mt++)
                ldsm_x4(af[mt], stg + OFF_A + swz(a_row + mt * 16, 2 * k2 + a_ch));
            // raw fp32 bits into tf32 MMA: HW uses upper 19 bits (implicit RZ on x)
            #pragma unroll
            for (int mt = 0; mt < 4; mt++)
                #pragma unroll
                for (int nt = 0; nt < 4; nt++)
                    mma_tf32(acc[mt][nt], af[mt],
                             bf[nt >> 1][(nt & 1) * 2], bf[nt >> 1][(nt & 1) * 2 + 1]);
        }
    }

    // -------- epilogue: y = x + acc + bias; softsign --------
    const int r  = lane >> 2;
    const int cq = (lane & 3) * 2;
    const float* xep = x + (size_t)bidx * TOK * DIMK;
    const float* bp  = bias + (size_t)day * DIMK;

    #pragma unroll
    for (int nt = 0; nt < 4; nt++) {
        const int n = n0 + nw + nt * 8 + cq;
        const float2 bb = *(const float2*)(bp + n);
        #pragma unroll
        for (int mt = 0; mt < 4; mt++) {
            const int m = m0 + mw + mt * 16 + r;
            const float2 x0 = __ldg((const float2*)(xep + (size_t)m * DIMK + n));
            const float2 x1 = __ldg((const float2*)(xep + (size_t)(m + 8) * DIMK + n));
            float y0 = acc[mt][nt][0] + x0.x + bb.x;
            float y1 = acc[mt][nt][1] + x0.y + bb.y;
            float y2 = acc[mt][nt][2] + x1.x + bb.x;
            float y3 = acc[mt][nt][3] + x1.y + bb.y;
            float2 o0, o1;
            o0.x = __fdividef(y0, 1.0f + fabsf(y0));
            o0.y = __fdividef(y1, 1.0f + fabsf(y1));
            o1.x = __fdividef(y2, 1.0f + fabsf(y2));
            o1.y = __fdividef(y3, 1.0f + fabsf(y3));
            *(float2*)(out + (size_t)bidx * TOK * DIMK + (size_t)m * DIMK + n)       = o0;
            *(float2*)(out + (size_t)bidx * TOK * DIMK + (size_t)(m + 8) * DIMK + n) = o1;
        }
    }
}

// ---------------- launch ----------------
extern "C" void kernel_launch(void* const* d_in, const int* in_sizes, int n_in,
                              void* d_out, int out_size)
{
    const float* x   = (const float*)d_in[0];
    const int*   day = (const int*)  d_in[1];
    const float* W   = (const float*)d_in[2];
    const float* b   = (const float*)d_in[3];
    float*       out = (float*)d_out;

    cudaFuncSetAttribute(day_adapter_tf32,
                         cudaFuncAttributeMaxDynamicSharedMemorySize, SMEM_TOTAL);

    prep_e_kernel<<<dim3(DIMK / 32, DIMK / 32, NDAYS), dim3(32, 8)>>>(W);

    dim3 grid(DIMK / CTA_N, TOK / CTA_M, NB);   // (4, 8, 64) = 2048 CTAs
    day_adapter_tf32<<<grid, NTHREADS, SMEM_TOTAL>>>(x, day, b, out);
}

// round 6
// speedup vs baseline: 2.8913x; 1.0493x over previous
#include <cuda_runtime.h>
#include <cuda_bf16.h>
#include <stdint.h>

// DayAdapter via tf32 mma.sync: y = softsign(x + x@E + b), E = W - I (|E|~0.02).
// Raw fp32 into tf32 MMA (HW truncates low mantissa); E pre-rounded RNA.
// 3-stage cp.async pipeline + register-level fragment double buffering so
// LDSM (smem) of next fragment group overlaps MMA (tensor) of current.

#define DIMK 512
#define TOK  1024
#define NB   64
#define NDAYS 24

#define CTA_M 128
#define CTA_N 128
#define BK    32
#define KSTEPS (DIMK / BK)       // 16
#define NTHREADS 256             // 8 warps: 2(m) x 4(n), warp tile 64x32
#define STAGES 3

#define STG_BYTES 32768          // A 16KB | B 16KB, rows 128B = 8 x 16B chunks
#define OFF_A 0
#define OFF_B 16384
#define SMEM_TOTAL (STAGES * STG_BYTES)   // 98304

__device__ float g_Et[(size_t)NDAYS * DIMK * DIMK];   // E^T [day][n][k], tf32-rounded

// ---------------- helpers ----------------
__device__ __forceinline__ uint32_t smem_u32(const void* p) {
    return (uint32_t)__cvta_generic_to_shared(p);
}
__device__ __forceinline__ uint32_t swz(uint32_t row, uint32_t ch) {
    return row * 128u + ((ch ^ (row & 7u)) << 4);
}
__device__ __forceinline__ void ldsm_x4(uint32_t* r, uint32_t addr) {
    asm volatile("ldmatrix.sync.aligned.m8n8.x4.shared.b16 {%0,%1,%2,%3}, [%4];"
                 : "=r"(r[0]), "=r"(r[1]), "=r"(r[2]), "=r"(r[3]) : "r"(addr));
}
__device__ __forceinline__ void mma_tf32(float* c, const uint32_t* a, uint32_t b0, uint32_t b1) {
    asm volatile(
        "mma.sync.aligned.m16n8k8.row.col.f32.tf32.tf32.f32 "
        "{%0,%1,%2,%3}, {%4,%5,%6,%7}, {%8,%9}, {%0,%1,%2,%3};"
        : "+f"(c[0]), "+f"(c[1]), "+f"(c[2]), "+f"(c[3])
        : "r"(a[0]), "r"(a[1]), "r"(a[2]), "r"(a[3]), "r"(b0), "r"(b1));
}
__device__ __forceinline__ uint32_t f2tf32(uint32_t v) {
    uint32_t o;
    asm("cvt.rna.tf32.f32 %0, %1;" : "=r"(o) : "r"(v));
    return o;
}
__device__ __forceinline__ void cp_async16(uint32_t dst, const void* src) {
    asm volatile("cp.async.cg.shared.global [%0], [%1], 16;" :: "r"(dst), "l"(src));
}
__device__ __forceinline__ void cp_commit() { asm volatile("cp.async.commit_group;"); }
__device__ __forceinline__ void cp_wait1()  { asm volatile("cp.async.wait_group 1;"); }

// ---------------- prep: Et[d][n][k] = tf32_rna(W[d][k][n] - (k==n)) ----------------
__global__ void prep_e_kernel(const float* __restrict__ W) {
    __shared__ float t[32][33];
    const int d  = blockIdx.z;
    const int k0 = blockIdx.y * 32;
    const int n0 = blockIdx.x * 32;
    const float* Wd = W + (size_t)d * DIMK * DIMK;
    #pragma unroll
    for (int i = threadIdx.y; i < 32; i += 8)
        t[i][threadIdx.x] = Wd[(size_t)(k0 + i) * DIMK + n0 + threadIdx.x];
    __syncthreads();
    #pragma unroll
    for (int i = threadIdx.y; i < 32; i += 8) {
        const int k = k0 + threadIdx.x;
        const int n = n0 + i;
        float v = t[threadIdx.x][i] - ((k == n) ? 1.0f : 0.0f);
        uint32_t r = f2tf32(__float_as_uint(v));
        g_Et[((size_t)d * DIMK + n) * DIMK + k] = __uint_as_float(r);
    }
}

// ---------------- main ----------------
__global__ void __launch_bounds__(NTHREADS, 2)
day_adapter_tf32(const float* __restrict__ x,
                 const int*   __restrict__ day_w,
                 const float* __restrict__ bias,
                 float*       __restrict__ out)
{
    extern __shared__ char smem[];
    const uint32_t sb = smem_u32(smem);
    const int tid  = threadIdx.x;
    const int wid  = tid >> 5;
    const int lane = tid & 31;

    const int n0   = blockIdx.x * CTA_N;
    const int m0   = blockIdx.y * CTA_M;
    const int bidx = blockIdx.z;

    // robust day_ids decode (int32 vs int64 buffer)
    int is64 = 1;
    #pragma unroll 8
    for (int i = 1; i < 64; i += 2)
        if (__ldg(day_w + i) != 0) is64 = 0;
    const int day = is64 ? __ldg(day_w + 2 * bidx) : __ldg(day_w + bidx);

    // -------- stage loaders: thread t -> row=t>>1, chunks (t&1)*4 .. +3 --------
    const int lrow = tid >> 1;
    const int lc0  = (tid & 1) * 4;
    const float* agp = x    + ((size_t)bidx * TOK + m0 + lrow) * DIMK + lc0 * 4;
    const float* bgp = g_Et + ((size_t)day  * DIMK + n0 + lrow) * DIMK + lc0 * 4;
    const uint32_t lso = swz(lrow, lc0), lso1 = swz(lrow, lc0 + 1),
                   lso2 = swz(lrow, lc0 + 2), lso3 = swz(lrow, lc0 + 3);

    auto LOAD_STAGE = [&](uint32_t stg, int s) {
        const float* asrc = agp + s * BK;
        const float* bsrc = bgp + s * BK;
        cp_async16(stg + OFF_A + lso,  asrc);
        cp_async16(stg + OFF_A + lso1, asrc + 4);
        cp_async16(stg + OFF_A + lso2, asrc + 8);
        cp_async16(stg + OFF_A + lso3, asrc + 12);
        cp_async16(stg + OFF_B + lso,  bsrc);
        cp_async16(stg + OFF_B + lso1, bsrc + 4);
        cp_async16(stg + OFF_B + lso2, bsrc + 8);
        cp_async16(stg + OFF_B + lso3, bsrc + 12);
    };

    // -------- warp tile --------
    const int mw = (wid >> 2) * 64;
    const int nw = (wid & 3) * 32;

    float acc[4][4][4];
    #pragma unroll
    for (int i = 0; i < 4; i++)
        #pragma unroll
        for (int j = 0; j < 4; j++)
            #pragma unroll
            for (int q = 0; q < 4; q++) acc[i][j][q] = 0.0f;

    // ldmatrix lane addressing
    const int a_row = mw + (lane & 15);                       // + mt*16
    const int a_ch  = lane >> 4;                              // + 2*k2
    const int b_row = nw + (lane & 7) + ((lane >> 4) << 3);   // + np*16
    const int b_ch  = (lane >> 3) & 1;                        // + 2*k2

    // -------- prolog --------
    LOAD_STAGE(sb + 0 * STG_BYTES, 0); cp_commit();
    LOAD_STAGE(sb + 1 * STG_BYTES, 1); cp_commit();

    int slotC = 0;   // consume slot for stage s
    int slotP = 2;   // produce slot for stage s+2

    // -------- main loop: one barrier per stage, pipelined fragments --------
    #pragma unroll 1
    for (int s = 0; s < KSTEPS; s++) {
        cp_wait1();
        __syncthreads();

        const uint32_t stg  = sb + slotC * STG_BYTES;
        const uint32_t stgA = stg + OFF_A;
        const uint32_t stgB = stg + OFF_B;

        // fragment register double buffers
        uint32_t bf[2][8];
        uint32_t af[2][4];

        // preload k2=0 fragments (B both halves, A mt=0)
        ldsm_x4(bf[0] + 0, stgB + swz(b_row,      b_ch));
        ldsm_x4(bf[0] + 4, stgB + swz(b_row + 16, b_ch));
        ldsm_x4(af[0],     stgA + swz(a_row,      a_ch));

        // issue next-stage global loads now (overlaps with MMAs below)
        if (s + 2 < KSTEPS) LOAD_STAGE(sb + slotP * STG_BYTES, s + 2);
        cp_commit();

        int ab = 0;   // A-fragment buffer parity
        #pragma unroll
        for (int k2 = 0; k2 < 4; k2++) {
            const int cur = k2 & 1;
            // prefetch next k2's B fragments
            if (k2 < 3) {
                ldsm_x4(bf[cur ^ 1] + 0, stgB + swz(b_row,      2 * (k2 + 1) + b_ch));
                ldsm_x4(bf[cur ^ 1] + 4, stgB + swz(b_row + 16, 2 * (k2 + 1) + b_ch));
            }
            #pragma unroll
            for (int mt = 0; mt < 4; mt++) {
                // prefetch next A fragment (mt+1, or k2+1's mt=0)
                if (mt < 3)
                    ldsm_x4(af[ab ^ 1], stgA + swz(a_row + (mt + 1) * 16, 2 * k2 + a_ch));
                else if (k2 < 3)
                    ldsm_x4(af[ab ^ 1], stgA + swz(a_row, 2 * (k2 + 1) + a_ch));
                #pragma unroll
                for (int nt = 0; nt < 4; nt++)
                    mma_tf32(acc[mt][nt], af[ab],
                             bf[cur][(nt >> 1) * 4 + (nt & 1) * 2],
                             bf[cur][(nt >> 1) * 4 + (nt & 1) * 2 + 1]);
                ab ^= 1;
            }
        }

        slotC = (slotC == STAGES - 1) ? 0 : slotC + 1;
        slotP = (slotP == STAGES - 1) ? 0 : slotP + 1;
    }

    // -------- epilogue: y = x + acc + bias; softsign --------
    const int r  = lane >> 2;
    const int cq = (lane & 3) * 2;
    const float* xep = x + (size_t)bidx * TOK * DIMK;
    const float* bp  = bias + (size_t)day * DIMK;

    #pragma unroll
    for (int nt = 0; nt < 4; nt++) {
        const int n = n0 + nw + nt * 8 + cq;
        const float2 bb = *(const float2*)(bp + n);
        #pragma unroll
        for (int mt = 0; mt < 4; mt++) {
            const int m = m0 + mw + mt * 16 + r;
            const float2 x0 = __ldg((const float2*)(xep + (size_t)m * DIMK + n));
            const float2 x1 = __ldg((const float2*)(xep + (size_t)(m + 8) * DIMK + n));
            float y0 = acc[mt][nt][0] + x0.x + bb.x;
            float y1 = acc[mt][nt][1] + x0.y + bb.y;
            float y2 = acc[mt][nt][2] + x1.x + bb.x;
            float y3 = acc[mt][nt][3] + x1.y + bb.y;
            float2 o0, o1;
            o0.x = __fdividef(y0, 1.0f + fabsf(y0));
            o0.y = __fdividef(y1, 1.0f + fabsf(y1));
            o1.x = __fdividef(y2, 1.0f + fabsf(y2));
            o1.y = __fdividef(y3, 1.0f + fabsf(y3));
            *(float2*)(out + (size_t)bidx * TOK * DIMK + (size_t)m * DIMK + n)       = o0;
            *(float2*)(out + (size_t)bidx * TOK * DIMK + (size_t)(m + 8) * DIMK + n) = o1;
        }
    }
}

// ---------------- launch ----------------
extern "C" void kernel_launch(void* const* d_in, const int* in_sizes, int n_in,
                              void* d_out, int out_size)
{
    const float* x   = (const float*)d_in[0];
    const int*   day = (const int*)  d_in[1];
    const float* W   = (const float*)d_in[2];
    const float* b   = (const float*)d_in[3];
    float*       out = (float*)d_out;

    cudaFuncSetAttribute(day_adapter_tf32,
                         cudaFuncAttributeMaxDynamicSharedMemorySize, SMEM_TOTAL);

    prep_e_kernel<<<dim3(DIMK / 32, DIMK / 32, NDAYS), dim3(32, 8)>>>(W);

    dim3 grid(DIMK / CTA_N, TOK / CTA_M, NB);   // (4, 8, 64) = 2048 CTAs
    day_adapter_tf32<<<grid, NTHREADS, SMEM_TOTAL>>>(x, day, b, out);
}